// round 2
// baseline (speedup 1.0000x reference)
#include <cuda_runtime.h>

#define NTH     128
#define OUT_Y   8
#define TILE_X  256            // output columns per block (2 per thread)
#define HALO    8
#define SM_W    (TILE_X + HALO)  // 264
#define SM_H    (OUT_Y + HALO)   // 16
#define IH 4096
#define IW 4096
#define KH 9
#define KW 9
#define OH (IH - KH + 1)         // 4088
#define OW (IW - KW + 1)         // 4088

typedef unsigned long long u64;

__device__ __forceinline__ u64 ffma2(u64 a, u64 b, u64 c) {
    u64 d;
    asm("fma.rn.f32x2 %0, %1, %2, %3;" : "=l"(d) : "l"(a), "l"(b), "l"(c));
    return d;
}
__device__ __forceinline__ u64 pack2(float lo, float hi) {
    u64 d;
    asm("mov.b64 %0, {%1, %2};" : "=l"(d) : "f"(lo), "f"(hi));
    return d;
}
__device__ __forceinline__ float f2hi(u64 a) {
    float lo, hi;
    asm("mov.b64 {%0, %1}, %2;" : "=f"(lo), "=f"(hi) : "l"(a));
    return hi;
}
__device__ __forceinline__ float f2lo(u64 a) {
    float lo, hi;
    asm("mov.b64 {%0, %1}, %2;" : "=f"(lo), "=f"(hi) : "l"(a));
    return lo;
}

__global__ __launch_bounds__(NTH)
void conv9x9_f32x2(const float* __restrict__ X,
                   const float* __restrict__ Kw,
                   const float* __restrict__ Bias,
                   float* __restrict__ Out)
{
    __shared__ __align__(16) float sX[SM_H][SM_W];
    __shared__ float sK[KH * KW];

    const int tid = threadIdx.x;
    const int x0  = blockIdx.x * TILE_X;
    const int y0  = blockIdx.y * OUT_Y;

    if (tid < KH * KW) sK[tid] = Kw[tid];

    // Cooperative tile load (clamp to zero outside input; output masked later)
    for (int idx = tid; idx < SM_H * SM_W; idx += NTH) {
        const int r = idx / SM_W;
        const int c = idx - r * SM_W;
        const int gy = y0 + r;
        const int gx = x0 + c;
        float v = 0.0f;
        if (gy < IH && gx < IW) v = X[(long)gy * IW + gx];
        sX[r][c] = v;
    }
    __syncthreads();

    const float bias = Bias[0];
    u64 acc[OUT_Y];
    #pragma unroll
    for (int i = 0; i < OUT_Y; i++) acc[i] = pack2(bias, bias);

    const int cx = 2 * tid;   // even -> 8B-aligned pair base
    u64 E[SM_H];

    #pragma unroll
    for (int kxe = 0; kxe < KW; kxe += 2) {
        // ---- even kx = kxe: aligned 64-bit shared loads, no packing ----
        #pragma unroll
        for (int r = 0; r < SM_H; r++)
            E[r] = *(const u64*)&sX[r][cx + kxe];

        #pragma unroll
        for (int ky = 0; ky < KH; ky++) {
            const float w = sK[ky * KW + kxe];
            const u64 w2 = pack2(w, w);
            #pragma unroll
            for (int i = 0; i < OUT_Y; i++)
                acc[i] = ffma2(w2, E[i + ky], acc[i]);
        }

        // ---- odd kx = kxe+1: shift pair window by one scalar ----
        if (kxe + 1 < KW) {
            #pragma unroll
            for (int r = 0; r < SM_H; r++) {
                const float nx = sX[r][cx + kxe + 2];
                E[r] = pack2(f2hi(E[r]), nx);
            }
            #pragma unroll
            for (int ky = 0; ky < KH; ky++) {
                const float w = sK[ky * KW + kxe + 1];
                const u64 w2 = pack2(w, w);
                #pragma unroll
                for (int i = 0; i < OUT_Y; i++)
                    acc[i] = ffma2(w2, E[i + ky], acc[i]);
            }
        }
    }

    // Store: pairs are even-aligned and OW is even -> a pair is fully in or out
    const int gx = x0 + cx;
    if (gx < OW) {
        #pragma unroll
        for (int i = 0; i < OUT_Y; i++) {
            const int gy = y0 + i;   // grid.y * OUT_Y == OH exactly (511*8=4088)
            float2 o = make_float2(f2lo(acc[i]), f2hi(acc[i]));
            *(float2*)&Out[(long)gy * OW + gx] = o;
        }
    }
}

extern "C" void kernel_launch(void* const* d_in, const int* in_sizes, int n_in,
                              void* d_out, int out_size)
{
    const float* X    = (const float*)d_in[0];
    const float* Kw   = (const float*)d_in[1];
    const float* Bias = (const float*)d_in[2];
    float* Out        = (float*)d_out;

    dim3 grid((OW + TILE_X - 1) / TILE_X, (OH + OUT_Y - 1) / OUT_Y);
    dim3 block(NTH);
    conv9x9_f32x2<<<grid, block>>>(X, Kw, Bias, Out);
}

// round 4
// speedup vs baseline: 2.7650x; 2.7650x over previous
#include <cuda_runtime.h>
#include <cstdint>

#define IH 4096
#define IW 4096
#define OW 4088
#define NTH 128
#define XTILE 512
#define RSTRIP 73
#define ITERS 81          // RSTRIP + 8 input rows per strip
#define RING 16
#define ROWF 544          // padded floats per ring row (520 used)
#define PF 6

__device__ __forceinline__ uint32_t cvt_tf32(float f) {
    uint32_t r;
    asm("cvt.rna.tf32.f32 %0, %1;" : "=r"(r) : "f"(f));
    return r;
}

__device__ __forceinline__ void mma8(float* d,
                                     uint32_t a0, uint32_t a1, uint32_t a2, uint32_t a3,
                                     uint32_t b0, uint32_t b1) {
    asm("mma.sync.aligned.m16n8k8.row.col.f32.tf32.tf32.f32 "
        "{%0,%1,%2,%3}, {%4,%5,%6,%7}, {%8,%9}, {%0,%1,%2,%3};"
        : "+f"(d[0]), "+f"(d[1]), "+f"(d[2]), "+f"(d[3])
        : "r"(a0), "r"(a1), "r"(a2), "r"(a3), "r"(b0), "r"(b1));
}

__device__ __forceinline__ uint32_t s2u(const void* p) {
    uint32_t a;
    asm("{ .reg .u64 t; cvta.to.shared.u64 t, %1; cvt.u32.u64 %0, t; }" : "=r"(a) : "l"(p));
    return a;
}

__device__ __forceinline__ void cpa16(uint32_t dst, const void* src, uint32_t sz) {
    asm volatile("cp.async.ca.shared.global [%0], [%1], 16, %2;"
                 :: "r"(dst), "l"(src), "r"(sz) : "memory");
}

// one sliding-window iteration over input row R (RR = R mod 9, static)
#define ITER_BODY(R, RR, CLO, CHI) do {                                          \
    asm volatile("cp.async.wait_group %0;" :: "n"(PF-1) : "memory");             \
    __syncthreads();                                                             \
    {   const int p = (R) + PF;                                                  \
        if (p < ITERS) {                                                         \
            const float* srow = X + (size_t)(ybase + p) * IW + xb;               \
            uint32_t drow = smb + (uint32_t)((p & (RING-1)) * ROWF) * 4u;        \
            for (int j = tid; j < 130; j += NTH) {                               \
                uint32_t sz = (xb + 4*j + 3 < IW) ? 16u : 0u;                    \
                cpa16(drow + 16u*(uint32_t)j, srow + 4*j, sz);                   \
            }                                                                    \
        }                                                                        \
        asm volatile("cp.async.commit_group;" ::: "memory");                     \
    }                                                                            \
    const int rbase = ((R) & (RING-1)) * ROWF + wxb + 8*g4 + t4;                 \
    uint32_t a0 = cvt_tf32(sR[rbase]);                                           \
    uint32_t a1 = cvt_tf32(sR[rbase + 64]);                                      \
    uint32_t a2 = cvt_tf32(sR[rbase + 4]);                                       \
    uint32_t a3 = cvt_tf32(sR[rbase + 68]);                                      \
    uint32_t a4 = cvt_tf32(sR[rbase + 8]);                                       \
    uint32_t a5 = cvt_tf32(sR[rbase + 72]);                                      \
    uint32_t a6 = cvt_tf32(sR[rbase + 12]);                                      \
    uint32_t a7 = cvt_tf32(sR[rbase + 76]);                                      \
    _Pragma("unroll")                                                            \
    for (int ky = 0; ky < 9; ky++) {                                             \
        const int y = (R) - ky;                                                  \
        if ((!(CLO) || y >= 0) && (!(CHI) || y < RSTRIP)) {                      \
            const int s = ((RR) - ky + 9) % 9;                                   \
            mma8(acc[s], a0, a1, a2, a3, bf[ky][0][0], bf[ky][0][1]);            \
            mma8(acc[s], a4, a5, a6, a7, bf[ky][1][0], bf[ky][1][1]);            \
        }                                                                        \
    }                                                                            \
    {   const int y = (R) - 8;                                                   \
        if (!(CLO) || y >= 0) {                                                  \
            const int s = ((RR) + 1) % 9;                                        \
            const int gy = ybase + y;                                            \
            const int gxa = xb + wxb + 8*g4 + 2*t4;                              \
            if (gxa < OW) {                                                      \
                float2 v; v.x = acc[s][0]; v.y = acc[s][1];                      \
                *(float2*)(Out + (size_t)gy*OW + gxa) = v;                       \
            }                                                                    \
            if (gxa + 64 < OW) {                                                 \
                float2 v; v.x = acc[s][2]; v.y = acc[s][3];                      \
                *(float2*)(Out + (size_t)gy*OW + gxa + 64) = v;                  \
            }                                                                    \
            _Pragma("unroll")                                                    \
            for (int q = 0; q < 4; q++) acc[s][q] = bias;                        \
        }                                                                        \
    }                                                                            \
} while (0)

__global__ void __launch_bounds__(NTH)
conv9x9_mma(const float* __restrict__ X, const float* __restrict__ Kw,
            const float* __restrict__ Bias, float* __restrict__ Out)
{
    __shared__ __align__(16) float sR[RING * ROWF];

    const int tid  = threadIdx.x;
    const int lane = tid & 31;
    const int g4   = lane >> 2;   // groupID
    const int t4   = lane & 3;    // thread-in-group
    const int wxb  = (tid >> 5) * 128;
    const int xb   = blockIdx.x * XTILE;
    const int ybase = blockIdx.y * RSTRIP;
    const uint32_t smb = s2u(sR);

    const float bias = Bias[0];

    // Toeplitz B fragments: B[k,n] = w[ky, k - n], k = 8c + t4 (+4), n = g4
    uint32_t bf[9][2][2];
    #pragma unroll
    for (int ky = 0; ky < 9; ky++) {
        #pragma unroll
        for (int c = 0; c < 2; c++) {
            const int kx0 = 8*c + t4 - g4;
            const int kx1 = kx0 + 4;
            float w0 = (kx0 >= 0 && kx0 < 9) ? Kw[ky*9 + kx0] : 0.0f;
            float w1 = (kx1 >= 0 && kx1 < 9) ? Kw[ky*9 + kx1] : 0.0f;
            bf[ky][c][0] = cvt_tf32(w0);
            bf[ky][c][1] = cvt_tf32(w1);
        }
    }

    float acc[9][4];
    #pragma unroll
    for (int s = 0; s < 9; s++)
        #pragma unroll
        for (int q = 0; q < 4; q++) acc[s][q] = bias;

    // prologue: prefetch input rows 0..PF-1, one commit group each
    for (int p = 0; p < PF; p++) {
        const float* srow = X + (size_t)(ybase + p) * IW + xb;
        uint32_t drow = smb + (uint32_t)((p & (RING-1)) * ROWF) * 4u;
        for (int j = tid; j < 130; j += NTH) {
            uint32_t sz = (xb + 4*j + 3 < IW) ? 16u : 0u;
            cpa16(drow + 16u*(uint32_t)j, srow + 4*j, sz);
        }
        asm volatile("cp.async.commit_group;" ::: "memory");
    }

    // block 0: r = 0..8 (need y>=0 checks; y < RSTRIP trivially true)
    #pragma unroll
    for (int rr = 0; rr < 9; rr++) ITER_BODY(rr, rr, true, false);

    // middle blocks: r = 9..71, all y in [1,72) valid
    for (int rb = 9; rb <= 63; rb += 9) {
        #pragma unroll
        for (int rr = 0; rr < 9; rr++) ITER_BODY(rb + rr, rr, false, false);
    }

    // last block: r = 72..80 (need y < RSTRIP checks)
    #pragma unroll
    for (int rr = 0; rr < 9; rr++) ITER_BODY(72 + rr, rr, false, true);
}

extern "C" void kernel_launch(void* const* d_in, const int* in_sizes, int n_in,
                              void* d_out, int out_size)
{
    const float* X    = (const float*)d_in[0];
    const float* Kw   = (const float*)d_in[1];
    const float* Bias = (const float*)d_in[2];
    float* Out        = (float*)d_out;

    dim3 grid(8, 56);   // 8 x-tiles of 512 cols, 56 y-strips of 73 rows
    dim3 block(NTH);
    conv9x9_mma<<<grid, block>>>(X, Kw, Bias, Out);
}